// round 4
// baseline (speedup 1.0000x reference)
#include <cuda_runtime.h>
#include <cstdint>

// Problem constants
#define NGRAPH 128
#define NODES  256
#define CH     64
#define ADJ_ELEMS   ((size_t)NGRAPH * NODES * NODES)   // 8388608
#define F_ELEMS     ((size_t)NGRAPH * NODES * CH)      // 2097152
#define F_BASE      (3 * ADJ_ELEMS)                    // 25165824
#define STR 68   // smem row stride (floats): (4*g8+q) bank pattern, conflict-free

__device__ __forceinline__ float tf32r(float x) {
    uint32_t u;
    asm("cvt.rna.tf32.f32 %0, %1;" : "=r"(u) : "f"(x));
    return __uint_as_float(u);
}

__device__ __forceinline__ void mma_tf32(float d[4], const uint32_t a[4], const uint32_t b[2]) {
    asm volatile(
        "mma.sync.aligned.m16n8k8.row.col.f32.tf32.tf32.f32 "
        "{%0,%1,%2,%3},{%4,%5,%6,%7},{%8,%9},{%0,%1,%2,%3};\n"
        : "+f"(d[0]), "+f"(d[1]), "+f"(d[2]), "+f"(d[3])
        : "r"(a[0]), "r"(a[1]), "r"(a[2]), "r"(a[3]),
          "r"(b[0]), "r"(b[1]));
}

__device__ __forceinline__ float sigmoid_fast(float x) {
    return __fdividef(1.0f, 1.0f + __expf(-x));
}

// One MLP layer for this warp's 32 rows (two 16-row m-tiles), 3xTF32.
// FINAL=false: write fp32 h back into sF (in place, own rows only).
// FINAL=true : write fp32 F to gmem, tf32-rounded F into sF.
__device__ __forceinline__ void mlp_layer(
    float* __restrict__ sF, const float* __restrict__ Whi, const float* __restrict__ Wlo,
    const float* __restrict__ bias, int row0, int g8, int q,
    bool final_layer, float* __restrict__ fout)
{
    float acc[2][8][4];
#pragma unroll
    for (int mt = 0; mt < 2; ++mt)
#pragma unroll
        for (int nt = 0; nt < 8; ++nt)
#pragma unroll
            for (int e = 0; e < 4; ++e) acc[mt][nt][e] = 0.0f;

#pragma unroll
    for (int k0 = 0; k0 < 8; ++k0) {
        const int kc = k0 * 8 + q;
        uint32_t ahi[2][4], alo[2][4];
#pragma unroll
        for (int mt = 0; mt < 2; ++mt) {
            const int r = row0 + mt * 16 + g8;
            float a0 = sF[r * STR + kc];
            float a1 = sF[(r + 8) * STR + kc];
            float a2 = sF[r * STR + kc + 4];
            float a3 = sF[(r + 8) * STR + kc + 4];
            float h0 = tf32r(a0), h1 = tf32r(a1), h2 = tf32r(a2), h3 = tf32r(a3);
            ahi[mt][0] = __float_as_uint(h0); ahi[mt][1] = __float_as_uint(h1);
            ahi[mt][2] = __float_as_uint(h2); ahi[mt][3] = __float_as_uint(h3);
            alo[mt][0] = __float_as_uint(tf32r(a0 - h0));
            alo[mt][1] = __float_as_uint(tf32r(a1 - h1));
            alo[mt][2] = __float_as_uint(tf32r(a2 - h2));
            alo[mt][3] = __float_as_uint(tf32r(a3 - h3));
        }
#pragma unroll
        for (int nt = 0; nt < 8; ++nt) {
            const int bo = (nt * 8 + g8) * STR + kc;
            uint32_t bhi[2] = {__float_as_uint(Whi[bo]), __float_as_uint(Whi[bo + 4])};
            uint32_t blo[2] = {__float_as_uint(Wlo[bo]), __float_as_uint(Wlo[bo + 4])};
#pragma unroll
            for (int mt = 0; mt < 2; ++mt) {
                mma_tf32(acc[mt][nt], ahi[mt], bhi);
                mma_tf32(acc[mt][nt], alo[mt], bhi);
                mma_tf32(acc[mt][nt], ahi[mt], blo);
            }
        }
    }
    __syncwarp();   // all lanes done reading this warp's sF rows

#pragma unroll
    for (int mt = 0; mt < 2; ++mt) {
        const int r = row0 + mt * 16 + g8;
#pragma unroll
        for (int nt = 0; nt < 8; ++nt) {
            const int c0 = nt * 8 + 2 * q;
            float v0 = fmaxf(acc[mt][nt][0] + bias[c0],     0.0f);
            float v1 = fmaxf(acc[mt][nt][1] + bias[c0 + 1], 0.0f);
            float v2 = fmaxf(acc[mt][nt][2] + bias[c0],     0.0f);
            float v3 = fmaxf(acc[mt][nt][3] + bias[c0 + 1], 0.0f);
            if (!final_layer) {
                *(float2*)&sF[r * STR + c0]       = make_float2(v0, v1);
                *(float2*)&sF[(r + 8) * STR + c0] = make_float2(v2, v3);
            } else {
                *(float2*)&fout[(size_t)r * CH + c0]       = make_float2(v0, v1);
                *(float2*)&fout[(size_t)(r + 8) * CH + c0] = make_float2(v2, v3);
                *(float2*)&sF[r * STR + c0]       = make_float2(tf32r(v0), tf32r(v1));
                *(float2*)&sF[(r + 8) * STR + c0] = make_float2(tf32r(v2), tf32r(v3));
            }
        }
    }
    __syncwarp();   // epilogue stores done before next phase's reads
}

// ---------------------------------------------------------------------------
// Fused kernel, 256 threads (8 warps), 2 CTAs/SM.
// smem: sF [256][STR] + one layer of hi/lo weights [2][64][STR] + biases.
// Phases: load z+W1 -> layer1 -> reload W2 -> layer2(+F out) -> adjacency
//         (4 chunks of 128x128, warp tile 64x32).
// ---------------------------------------------------------------------------
__global__ void __launch_bounds__(256, 2) fused_kernel(
    const float* __restrict__ z,
    const float* __restrict__ Wa1, const float* __restrict__ ba1,
    const float* __restrict__ Wa2, const float* __restrict__ ba2,
    const float* __restrict__ Wb1, const float* __restrict__ bb1,
    const float* __restrict__ Wb2, const float* __restrict__ bb2,
    const float* __restrict__ Wt1, const float* __restrict__ bt1,
    const float* __restrict__ Wt2, const float* __restrict__ bt2,
    float* __restrict__ out)
{
    extern __shared__ __align__(16) float smem[];
    float* sF   = smem;                 // [256][STR]
    float* sWhi = smem + 256 * STR;     // [64][STR] current layer hi
    float* sWlo = sWhi + 64 * STR;      // [64][STR] current layer lo
    float* sBias = sWlo + 64 * STR;     // [128] both biases

    const int g    = blockIdx.x;
    const int type = blockIdx.y;

    const float *W1, *B1, *W2, *B2;
    if (type == 0)      { W1 = Wa1; B1 = ba1; W2 = Wa2; B2 = ba2; }
    else if (type == 1) { W1 = Wb1; B1 = bb1; W2 = Wb2; B2 = bb2; }
    else                { W1 = Wt1; B1 = bt1; W2 = Wt2; B2 = bt2; }

    const int tid = threadIdx.x;
    const int warp = tid >> 5, lane = tid & 31;
    const int g8 = lane >> 2, q = lane & 3;

    // ---------------- Phase 0: z + W1 ----------------
    const float* zG = z + (size_t)g * NODES * CH;
    for (int i = tid; i < NODES * CH / 4; i += 256) {       // 4096 float4s
        int r = i >> 4, c4 = (i & 15) * 4;
        *(float4*)&sF[r * STR + c4] = *(const float4*)&zG[r * CH + c4];
    }
    for (int i = tid; i < 64 * 64; i += 256) {
        int k = i >> 6, n = i & 63;
        float w = W1[i];                 // coalesced
        float hi = tf32r(w);
        sWhi[n * STR + k] = hi;          // transposed [n][k]
        sWlo[n * STR + k] = tf32r(w - hi);
    }
    if (tid < 64)       sBias[tid] = B1[tid];
    else if (tid < 128) sBias[tid] = B2[tid - 64];
    __syncthreads();

    // ---------------- Phase 1: layer 1 ----------------
    const int row0 = warp * 32;   // this warp owns rows [row0, row0+32)
    float* __restrict__ fout = out + F_BASE + (size_t)type * F_ELEMS
                                   + (size_t)g * NODES * CH;

    mlp_layer(sF, sWhi, sWlo, sBias, row0, g8, q, false, fout);
    __syncthreads();   // all warps done reading W1

    // ---------------- Phase 2: swap weights, layer 2 ----------------
    for (int i = tid; i < 64 * 64; i += 256) {
        int k = i >> 6, n = i & 63;
        float w = W2[i];
        float hi = tf32r(w);
        sWhi[n * STR + k] = hi;
        sWlo[n * STR + k] = tf32r(w - hi);
    }
    __syncthreads();

    mlp_layer(sF, sWhi, sWlo, sBias + 64, row0, g8, q, true, fout);
    __syncthreads();   // full F (tf32) visible to all warps

    // ---------------- Phase 3: adjacency, 4 chunks of 128x128 ----------------
    const int wm = (warp >> 2) * 64;    // 0 or 64 within chunk rows
    const int wn = (warp & 3) * 32;     // 0..96 within chunk cols
    float* __restrict__ O = out + ((size_t)type * NGRAPH + g) * (NODES * NODES);

#pragma unroll 1
    for (int tm = 0; tm < 2; ++tm) {
#pragma unroll 1
        for (int tn = 0; tn < 2; ++tn) {
            float acc[4][4][4];
#pragma unroll
            for (int mt = 0; mt < 4; ++mt)
#pragma unroll
                for (int nt = 0; nt < 4; ++nt)
#pragma unroll
                    for (int e = 0; e < 4; ++e) acc[mt][nt][e] = 0.0f;

#pragma unroll
            for (int k0 = 0; k0 < 8; ++k0) {
                const int kc = k0 * 8 + q;
                uint32_t af[4][4], bf[4][2];
#pragma unroll
                for (int mt = 0; mt < 4; ++mt) {
                    const float* p = &sF[(tm * 128 + wm + mt * 16 + g8) * STR + kc];
                    af[mt][0] = __float_as_uint(p[0]);
                    af[mt][2] = __float_as_uint(p[4]);
                    af[mt][1] = __float_as_uint(p[8 * STR]);
                    af[mt][3] = __float_as_uint(p[8 * STR + 4]);
                }
#pragma unroll
                for (int nt = 0; nt < 4; ++nt) {
                    const float* p = &sF[(tn * 128 + wn + nt * 8 + g8) * STR + kc];
                    bf[nt][0] = __float_as_uint(p[0]);
                    bf[nt][1] = __float_as_uint(p[4]);
                }
#pragma unroll
                for (int mt = 0; mt < 4; ++mt)
#pragma unroll
                    for (int nt = 0; nt < 4; ++nt)
                        mma_tf32(acc[mt][nt], af[mt], bf[nt]);
            }

#pragma unroll
            for (int mt = 0; mt < 4; ++mt) {
                const int row = tm * 128 + wm + mt * 16 + g8;
#pragma unroll
                for (int nt = 0; nt < 4; ++nt) {
                    const int col = tn * 128 + wn + nt * 8 + 2 * q;
                    float2 v0, v1;
                    v0.x = sigmoid_fast(acc[mt][nt][0]);
                    v0.y = sigmoid_fast(acc[mt][nt][1]);
                    v1.x = sigmoid_fast(acc[mt][nt][2]);
                    v1.y = sigmoid_fast(acc[mt][nt][3]);
                    *(float2*)&O[(size_t)row * NODES + col]       = v0;
                    *(float2*)&O[(size_t)(row + 8) * NODES + col] = v1;
                }
            }
        }
    }
}

extern "C" void kernel_launch(void* const* d_in, const int* in_sizes, int n_in,
                              void* d_out, int out_size) {
    const float* z   = (const float*)d_in[0];
    // d_in[1] = batch (int64): uniform segments, unused
    const float* Wa1 = (const float*)d_in[2];
    const float* ba1 = (const float*)d_in[3];
    const float* Wa2 = (const float*)d_in[4];
    const float* ba2 = (const float*)d_in[5];
    const float* Wb1 = (const float*)d_in[6];
    const float* bb1 = (const float*)d_in[7];
    const float* Wb2 = (const float*)d_in[8];
    const float* bb2 = (const float*)d_in[9];
    const float* Wt1 = (const float*)d_in[10];
    const float* bt1 = (const float*)d_in[11];
    const float* Wt2 = (const float*)d_in[12];
    const float* bt2 = (const float*)d_in[13];
    float* out = (float*)d_out;

    const int smem_bytes = (256 * STR + 2 * 64 * STR + 128) * (int)sizeof(float); // 104960
    cudaFuncSetAttribute(fused_kernel, cudaFuncAttributeMaxDynamicSharedMemorySize, smem_bytes);
    fused_kernel<<<dim3(NGRAPH, 3), 256, smem_bytes>>>(
        z, Wa1, ba1, Wa2, ba2, Wb1, bb1, Wb2, bb2, Wt1, bt1, Wt2, bt2, out);
}

// round 6
// speedup vs baseline: 1.2707x; 1.2707x over previous
#include <cuda_runtime.h>
#include <cstdint>

// Problem constants
#define NGRAPH 128
#define NODES  256
#define CH     64
#define ADJ_ELEMS   ((size_t)NGRAPH * NODES * NODES)   // 8388608
#define F_ELEMS     ((size_t)NGRAPH * NODES * CH)      // 2097152
#define F_BASE      (3 * ADJ_ELEMS)                    // 25165824
#define STR 68   // smem row stride (floats): (4*g8+q) bank pattern, conflict-free

__device__ __forceinline__ float tf32r(float x) {
    uint32_t u;
    asm("cvt.rna.tf32.f32 %0, %1;" : "=r"(u) : "f"(x));
    return __uint_as_float(u);
}

__device__ __forceinline__ void mma_tf32(float d[4], const uint32_t a[4], const uint32_t b[2]) {
    asm volatile(
        "mma.sync.aligned.m16n8k8.row.col.f32.tf32.tf32.f32 "
        "{%0,%1,%2,%3},{%4,%5,%6,%7},{%8,%9},{%0,%1,%2,%3};\n"
        : "+f"(d[0]), "+f"(d[1]), "+f"(d[2]), "+f"(d[3])
        : "r"(a[0]), "r"(a[1]), "r"(a[2]), "r"(a[3]),
          "r"(b[0]), "r"(b[1]));
}

__device__ __forceinline__ float sigmoid_fast(float x) {
    return __fdividef(1.0f, 1.0f + __expf(-x));
}

// ---------------------------------------------------------------------------
// Fused kernel, 512 threads (16 warps), 1 CTA/SM, grid (128,3) = 384 CTAs.
// R3 structure (best measured: 81.9us) with plain-tf32 single-pass MLP
// (2048 MLP MMAs/CTA instead of 6144) and both weight layers smem-resident.
// smem: sF [256][STR] + sW [2][64][STR] + bias[128] = 104448+512 B ~ 104.4 KB
// Phases: load -> layer1 -> layer2(+F out), warp-private, no block syncs
//         -> adjacency (two 128-row halves, warp tile 64x32).
// ---------------------------------------------------------------------------
__global__ void __launch_bounds__(512, 1) fused_kernel(
    const float* __restrict__ z,
    const float* __restrict__ Wa1, const float* __restrict__ ba1,
    const float* __restrict__ Wa2, const float* __restrict__ ba2,
    const float* __restrict__ Wb1, const float* __restrict__ bb1,
    const float* __restrict__ Wb2, const float* __restrict__ bb2,
    const float* __restrict__ Wt1, const float* __restrict__ bt1,
    const float* __restrict__ Wt2, const float* __restrict__ bt2,
    float* __restrict__ out)
{
    extern __shared__ __align__(16) float smem[];
    float* sF    = smem;                  // [256][STR] z -> h -> F(tf32)
    float* sW    = smem + 256 * STR;      // [2][64][STR] tf32 weights, transposed [n][k]
    float* sBias = sW + 2 * 64 * STR;     // [128]

    const int g    = blockIdx.x;
    const int type = blockIdx.y;

    const float *W1, *B1, *W2, *B2;
    if (type == 0)      { W1 = Wa1; B1 = ba1; W2 = Wa2; B2 = ba2; }
    else if (type == 1) { W1 = Wb1; B1 = bb1; W2 = Wb2; B2 = bb2; }
    else                { W1 = Wt1; B1 = bt1; W2 = Wt2; B2 = bt2; }

    const int tid = threadIdx.x;
    const int warp = tid >> 5, lane = tid & 31;
    const int g8 = lane >> 2, q = lane & 3;

    // ---------------- Phase 0: loads ----------------
    const float* zG = z + (size_t)g * NODES * CH;
    for (int i = tid; i < NODES * CH / 4; i += 512) {       // 4096 float4s
        int r = i >> 4, c4 = (i & 15) * 4;
        *(float4*)&sF[r * STR + c4] = *(const float4*)&zG[r * CH + c4];
    }
#pragma unroll 1
    for (int l = 0; l < 2; ++l) {
        const float* W = l ? W2 : W1;
        float* w = sW + l * 64 * STR;
        for (int i = tid; i < 64 * 64; i += 512) {
            int k = i >> 6, n = i & 63;
            w[n * STR + k] = tf32r(W[i]);   // coalesced read, transposed store
        }
    }
    if (tid < 64)       sBias[tid] = B1[tid];
    else if (tid < 128) sBias[tid] = B2[tid - 64];
    __syncthreads();

    // ---------------- Phase 1: MLP (warp-private 16 rows, no block syncs) ----
    const int row0 = warp * 16;
    float* __restrict__ fout = out + F_BASE + (size_t)type * F_ELEMS
                                   + (size_t)g * NODES * CH;

#pragma unroll 1
    for (int l = 0; l < 2; ++l) {
        const float* Wt   = sW + l * 64 * STR;
        const float* bias = sBias + l * 64;

        float acc[8][4];
#pragma unroll
        for (int nt = 0; nt < 8; ++nt)
#pragma unroll
            for (int e = 0; e < 4; ++e) acc[nt][e] = 0.0f;

#pragma unroll
        for (int k0 = 0; k0 < 8; ++k0) {
            const int kc = k0 * 8 + q;
            uint32_t af[4];
            af[0] = __float_as_uint(tf32r(sF[(row0 + g8)     * STR + kc]));
            af[1] = __float_as_uint(tf32r(sF[(row0 + g8 + 8) * STR + kc]));
            af[2] = __float_as_uint(tf32r(sF[(row0 + g8)     * STR + kc + 4]));
            af[3] = __float_as_uint(tf32r(sF[(row0 + g8 + 8) * STR + kc + 4]));
#pragma unroll
            for (int nt = 0; nt < 8; ++nt) {
                const int bo = (nt * 8 + g8) * STR + kc;
                uint32_t bf[2] = {__float_as_uint(Wt[bo]), __float_as_uint(Wt[bo + 4])};
                mma_tf32(acc[nt], af, bf);
            }
        }
        __syncwarp();   // all lanes done reading this warp's sF rows

#pragma unroll
        for (int nt = 0; nt < 8; ++nt) {
            const int c0 = nt * 8 + 2 * q;
            float v0 = fmaxf(acc[nt][0] + bias[c0],     0.0f);
            float v1 = fmaxf(acc[nt][1] + bias[c0 + 1], 0.0f);
            float v2 = fmaxf(acc[nt][2] + bias[c0],     0.0f);
            float v3 = fmaxf(acc[nt][3] + bias[c0 + 1], 0.0f);
            if (l == 0) {
                *(float2*)&sF[(row0 + g8)     * STR + c0] = make_float2(v0, v1);
                *(float2*)&sF[(row0 + g8 + 8) * STR + c0] = make_float2(v2, v3);
            } else {
                *(float2*)&fout[(size_t)(row0 + g8)     * CH + c0] = make_float2(v0, v1);
                *(float2*)&fout[(size_t)(row0 + g8 + 8) * CH + c0] = make_float2(v2, v3);
                *(float2*)&sF[(row0 + g8)     * STR + c0] = make_float2(tf32r(v0), tf32r(v1));
                *(float2*)&sF[(row0 + g8 + 8) * STR + c0] = make_float2(tf32r(v2), tf32r(v3));
            }
        }
        __syncwarp();   // stores visible before next layer's lane-crossed reads
    }
    __syncthreads();    // full F (tf32) visible to all warps

    // ---------------- Phase 3: adjacency ----------------
    const int wm2 = warp >> 3;          // 0..1 -> 64-row block within half
    const int wn  = (warp & 7) * 32;    // 0..224
    float* __restrict__ O = out + ((size_t)type * NGRAPH + g) * (NODES * NODES);

#pragma unroll 1
    for (int hm = 0; hm < 2; ++hm) {
        const int rbase = hm * 128 + wm2 * 64;

        float acc[4][4][4];
#pragma unroll
        for (int mt = 0; mt < 4; ++mt)
#pragma unroll
            for (int nt = 0; nt < 4; ++nt)
#pragma unroll
                for (int e = 0; e < 4; ++e) acc[mt][nt][e] = 0.0f;

#pragma unroll
        for (int k0 = 0; k0 < 8; ++k0) {
            const int kc = k0 * 8 + q;
            uint32_t af[4][4], bf[4][2];
#pragma unroll
            for (int mt = 0; mt < 4; ++mt) {
                const float* p = &sF[(rbase + mt * 16 + g8) * STR + kc];
                af[mt][0] = __float_as_uint(p[0]);
                af[mt][2] = __float_as_uint(p[4]);
                af[mt][1] = __float_as_uint(p[8 * STR]);
                af[mt][3] = __float_as_uint(p[8 * STR + 4]);
            }
#pragma unroll
            for (int nt = 0; nt < 4; ++nt) {
                const float* p = &sF[(wn + nt * 8 + g8) * STR + kc];
                bf[nt][0] = __float_as_uint(p[0]);
                bf[nt][1] = __float_as_uint(p[4]);
            }
#pragma unroll
            for (int mt = 0; mt < 4; ++mt)
#pragma unroll
                for (int nt = 0; nt < 4; ++nt)
                    mma_tf32(acc[mt][nt], af[mt], bf[nt]);
        }

#pragma unroll
        for (int mt = 0; mt < 4; ++mt) {
            const int row = rbase + mt * 16 + g8;
#pragma unroll
            for (int nt = 0; nt < 4; ++nt) {
                const int col = wn + nt * 8 + 2 * q;
                float2 v0, v1;
                v0.x = sigmoid_fast(acc[mt][nt][0]);
                v0.y = sigmoid_fast(acc[mt][nt][1]);
                v1.x = sigmoid_fast(acc[mt][nt][2]);
                v1.y = sigmoid_fast(acc[mt][nt][3]);
                *(float2*)&O[(size_t)row * NODES + col]       = v0;
                *(float2*)&O[(size_t)(row + 8) * NODES + col] = v1;
            }
        }
    }
}

extern "C" void kernel_launch(void* const* d_in, const int* in_sizes, int n_in,
                              void* d_out, int out_size) {
    const float* z   = (const float*)d_in[0];
    // d_in[1] = batch (int64): uniform segments, unused
    const float* Wa1 = (const float*)d_in[2];
    const float* ba1 = (const float*)d_in[3];
    const float* Wa2 = (const float*)d_in[4];
    const float* ba2 = (const float*)d_in[5];
    const float* Wb1 = (const float*)d_in[6];
    const float* bb1 = (const float*)d_in[7];
    const float* Wb2 = (const float*)d_in[8];
    const float* bb2 = (const float*)d_in[9];
    const float* Wt1 = (const float*)d_in[10];
    const float* bt1 = (const float*)d_in[11];
    const float* Wt2 = (const float*)d_in[12];
    const float* bt2 = (const float*)d_in[13];
    float* out = (float*)d_out;

    const int smem_bytes = (256 * STR + 2 * 64 * STR + 128) * (int)sizeof(float); // 104960
    cudaFuncSetAttribute(fused_kernel, cudaFuncAttributeMaxDynamicSharedMemorySize, smem_bytes);
    fused_kernel<<<dim3(NGRAPH, 3), 512, smem_bytes>>>(
        z, Wa1, ba1, Wa2, ba2, Wb1, bb1, Wb2, bb2, Wt1, bt1, Wt2, bt2, out);
}

// round 7
// speedup vs baseline: 1.3092x; 1.0303x over previous
#include <cuda_runtime.h>
#include <cstdint>

// Problem constants
#define NGRAPH 128
#define NODES  256
#define CH     64
#define ADJ_ELEMS   ((size_t)NGRAPH * NODES * NODES)   // 8388608
#define F_ELEMS     ((size_t)NGRAPH * NODES * CH)      // 2097152
#define F_BASE      (3 * ADJ_ELEMS)                    // 25165824
// smem row stride (floats). 72 -> 36 8B-words/row == 4 (mod 16), so LDS.64
// wavefront bank index = (4*g8 + q) mod 16: conflict-free.
#define STR 72

// k-dimension permutation: logical k -> physical slot, making (k, k+4)
// adjacent so fragment loads are single LDS.64.
__device__ __forceinline__ int posk(int k) {
    return (k & ~7) + ((k & 3) << 1) + ((k >> 2) & 1);
}

__device__ __forceinline__ float tf32r(float x) {
    uint32_t u;
    asm("cvt.rna.tf32.f32 %0, %1;" : "=r"(u) : "f"(x));
    return __uint_as_float(u);
}

__device__ __forceinline__ void mma_tf32(float d[4], const uint32_t a[4], const uint32_t b[2]) {
    asm volatile(
        "mma.sync.aligned.m16n8k8.row.col.f32.tf32.tf32.f32 "
        "{%0,%1,%2,%3},{%4,%5,%6,%7},{%8,%9},{%0,%1,%2,%3};\n"
        : "+f"(d[0]), "+f"(d[1]), "+f"(d[2]), "+f"(d[3])
        : "r"(a[0]), "r"(a[1]), "r"(a[2]), "r"(a[3]),
          "r"(b[0]), "r"(b[1]));
}

__device__ __forceinline__ float sigmoid_fast(float x) {
    return __fdividef(1.0f, 1.0f + __expf(-x));
}

// ---------------------------------------------------------------------------
// Fused kernel, 512 threads (16 warps), 1 CTA/SM, grid (128,3) = 384 CTAs.
// R6 structure (best: 69.6us) with paired-k smem layout: every fragment load
// in the MLP and adjacency hot loops is one LDS.64 instead of two LDS.32.
// Numerics are bit-identical to R6.
// smem: sF [256][STR] + sW [2][64][STR] + bias[128] = 111104 B
// ---------------------------------------------------------------------------
__global__ void __launch_bounds__(512, 1) fused_kernel(
    const float* __restrict__ z,
    const float* __restrict__ Wa1, const float* __restrict__ ba1,
    const float* __restrict__ Wa2, const float* __restrict__ ba2,
    const float* __restrict__ Wb1, const float* __restrict__ bb1,
    const float* __restrict__ Wb2, const float* __restrict__ bb2,
    const float* __restrict__ Wt1, const float* __restrict__ bt1,
    const float* __restrict__ Wt2, const float* __restrict__ bt2,
    float* __restrict__ out)
{
    extern __shared__ __align__(16) float smem[];
    float* sF    = smem;                  // [256][STR], k-permuted
    float* sW    = smem + 256 * STR;      // [2][64][STR] tf32 weights, [n][posk(k)]
    float* sBias = sW + 2 * 64 * STR;     // [128] (unpermuted, indexed by logical n)

    const int g    = blockIdx.x;
    const int type = blockIdx.y;

    const float *W1, *B1, *W2, *B2;
    if (type == 0)      { W1 = Wa1; B1 = ba1; W2 = Wa2; B2 = ba2; }
    else if (type == 1) { W1 = Wb1; B1 = bb1; W2 = Wb2; B2 = bb2; }
    else                { W1 = Wt1; B1 = bt1; W2 = Wt2; B2 = bt2; }

    const int tid = threadIdx.x;
    const int warp = tid >> 5, lane = tid & 31;
    const int g8 = lane >> 2, q = lane & 3;

    // ---------------- Phase 0: loads (scattered STS due to k-permutation) ---
    const float* zG = z + (size_t)g * NODES * CH;
    for (int i = tid; i < NODES * CH / 4; i += 512) {       // 4096 float4s
        int r = i >> 4, c4 = (i & 15) * 4;
        float4 v = *(const float4*)&zG[r * CH + c4];
        float* row = &sF[r * STR];
        row[posk(c4 + 0)] = v.x;
        row[posk(c4 + 1)] = v.y;
        row[posk(c4 + 2)] = v.z;
        row[posk(c4 + 3)] = v.w;
    }
#pragma unroll 1
    for (int l = 0; l < 2; ++l) {
        const float* W = l ? W2 : W1;
        float* w = sW + l * 64 * STR;
        for (int i = tid; i < 64 * 64; i += 512) {
            int k = i >> 6, n = i & 63;
            w[n * STR + posk(k)] = tf32r(W[i]);   // coalesced read, scattered store
        }
    }
    if (tid < 64)       sBias[tid] = B1[tid];
    else if (tid < 128) sBias[tid] = B2[tid - 64];
    __syncthreads();

    // ---------------- Phase 1: MLP (warp-private 16 rows, no block syncs) ----
    const int row0 = warp * 16;
    const int kq2 = 2 * q;   // physical offset of the (q, q+4) pair within a group
    float* __restrict__ fout = out + F_BASE + (size_t)type * F_ELEMS
                                   + (size_t)g * NODES * CH;

#pragma unroll 1
    for (int l = 0; l < 2; ++l) {
        const float* Wt   = sW + l * 64 * STR;
        const float* bias = sBias + l * 64;

        float acc[8][4];
#pragma unroll
        for (int nt = 0; nt < 8; ++nt)
#pragma unroll
            for (int e = 0; e < 4; ++e) acc[nt][e] = 0.0f;

#pragma unroll
        for (int k0 = 0; k0 < 8; ++k0) {
            const int kp = k0 * 8 + kq2;
            float2 la = *(const float2*)&sF[(row0 + g8)     * STR + kp];
            float2 lb = *(const float2*)&sF[(row0 + g8 + 8) * STR + kp];
            uint32_t af[4];
            af[0] = __float_as_uint(tf32r(la.x));   // A[g8][kc]
            af[1] = __float_as_uint(tf32r(lb.x));   // A[g8+8][kc]
            af[2] = __float_as_uint(tf32r(la.y));   // A[g8][kc+4]
            af[3] = __float_as_uint(tf32r(lb.y));   // A[g8+8][kc+4]
#pragma unroll
            for (int nt = 0; nt < 8; ++nt) {
                float2 wb = *(const float2*)&Wt[(nt * 8 + g8) * STR + kp];
                uint32_t bf[2] = {__float_as_uint(wb.x), __float_as_uint(wb.y)};
                mma_tf32(acc[nt], af, bf);
            }
        }
        __syncwarp();   // all lanes done reading this warp's sF rows

#pragma unroll
        for (int nt = 0; nt < 8; ++nt) {
            const int c0 = nt * 8 + 2 * q;
            const int p0 = posk(c0), p1 = posk(c0 + 1);
            float v0 = fmaxf(acc[nt][0] + bias[c0],     0.0f);
            float v1 = fmaxf(acc[nt][1] + bias[c0 + 1], 0.0f);
            float v2 = fmaxf(acc[nt][2] + bias[c0],     0.0f);
            float v3 = fmaxf(acc[nt][3] + bias[c0 + 1], 0.0f);
            float* rA = &sF[(row0 + g8) * STR];
            float* rB = &sF[(row0 + g8 + 8) * STR];
            if (l == 0) {
                rA[p0] = v0; rA[p1] = v1;
                rB[p0] = v2; rB[p1] = v3;
            } else {
                *(float2*)&fout[(size_t)(row0 + g8)     * CH + c0] = make_float2(v0, v1);
                *(float2*)&fout[(size_t)(row0 + g8 + 8) * CH + c0] = make_float2(v2, v3);
                rA[p0] = tf32r(v0); rA[p1] = tf32r(v1);
                rB[p0] = tf32r(v2); rB[p1] = tf32r(v3);
            }
        }
        __syncwarp();   // stores visible before next layer's lane-crossed reads
    }
    __syncthreads();    // full F (tf32, k-permuted) visible to all warps

    // ---------------- Phase 3: adjacency ----------------
    const int wm2 = warp >> 3;          // 0..1 -> 64-row block within half
    const int wn  = (warp & 7) * 32;    // 0..224
    float* __restrict__ O = out + ((size_t)type * NGRAPH + g) * (NODES * NODES);

#pragma unroll 1
    for (int hm = 0; hm < 2; ++hm) {
        const int rbase = hm * 128 + wm2 * 64;

        float acc[4][4][4];
#pragma unroll
        for (int mt = 0; mt < 4; ++mt)
#pragma unroll
            for (int nt = 0; nt < 4; ++nt)
#pragma unroll
                for (int e = 0; e < 4; ++e) acc[mt][nt][e] = 0.0f;

#pragma unroll
        for (int k0 = 0; k0 < 8; ++k0) {
            const int kp = k0 * 8 + kq2;
            uint32_t af[4][4], bf[4][2];
#pragma unroll
            for (int mt = 0; mt < 4; ++mt) {
                float2 la = *(const float2*)&sF[(rbase + mt * 16 + g8)     * STR + kp];
                float2 lb = *(const float2*)&sF[(rbase + mt * 16 + g8 + 8) * STR + kp];
                af[mt][0] = __float_as_uint(la.x);
                af[mt][1] = __float_as_uint(lb.x);
                af[mt][2] = __float_as_uint(la.y);
                af[mt][3] = __float_as_uint(lb.y);
            }
#pragma unroll
            for (int nt = 0; nt < 4; ++nt) {
                float2 vb = *(const float2*)&sF[(wn + nt * 8 + g8) * STR + kp];
                bf[nt][0] = __float_as_uint(vb.x);
                bf[nt][1] = __float_as_uint(vb.y);
            }
#pragma unroll
            for (int mt = 0; mt < 4; ++mt)
#pragma unroll
                for (int nt = 0; nt < 4; ++nt)
                    mma_tf32(acc[mt][nt], af[mt], bf[nt]);
        }

#pragma unroll
        for (int mt = 0; mt < 4; ++mt) {
            const int row = rbase + mt * 16 + g8;
#pragma unroll
            for (int nt = 0; nt < 4; ++nt) {
                const int col = wn + nt * 8 + 2 * q;
                float2 v0, v1;
                v0.x = sigmoid_fast(acc[mt][nt][0]);
                v0.y = sigmoid_fast(acc[mt][nt][1]);
                v1.x = sigmoid_fast(acc[mt][nt][2]);
                v1.y = sigmoid_fast(acc[mt][nt][3]);
                *(float2*)&O[(size_t)row * NODES + col]       = v0;
                *(float2*)&O[(size_t)(row + 8) * NODES + col] = v1;
            }
        }
    }
}

extern "C" void kernel_launch(void* const* d_in, const int* in_sizes, int n_in,
                              void* d_out, int out_size) {
    const float* z   = (const float*)d_in[0];
    // d_in[1] = batch (int64): uniform segments, unused
    const float* Wa1 = (const float*)d_in[2];
    const float* ba1 = (const float*)d_in[3];
    const float* Wa2 = (const float*)d_in[4];
    const float* ba2 = (const float*)d_in[5];
    const float* Wb1 = (const float*)d_in[6];
    const float* bb1 = (const float*)d_in[7];
    const float* Wb2 = (const float*)d_in[8];
    const float* bb2 = (const float*)d_in[9];
    const float* Wt1 = (const float*)d_in[10];
    const float* bt1 = (const float*)d_in[11];
    const float* Wt2 = (const float*)d_in[12];
    const float* bt2 = (const float*)d_in[13];
    float* out = (float*)d_out;

    const int smem_bytes = (256 * STR + 2 * 64 * STR + 128) * (int)sizeof(float); // 111104
    cudaFuncSetAttribute(fused_kernel, cudaFuncAttributeMaxDynamicSharedMemorySize, smem_bytes);
    fused_kernel<<<dim3(NGRAPH, 3), 512, smem_bytes>>>(
        z, Wa1, ba1, Wa2, ba2, Wb1, bb1, Wb2, bb2, Wt1, bt1, Wt2, bt2, out);
}